// round 11
// baseline (speedup 1.0000x reference)
#include <cuda_runtime.h>

#define BATCH 32
#define NIN   2312
#define NHID  512
#define NOUT  10
#define TT    350
#define TKLEN 100
#define NIG   73    // ceil(NIN/32) mask words per (b,t)
#define NHG   (NHID/32)

#define THETA 10.0f
#define D_SR  0.90483741803595952f     // exp(-0.1)
#define C_SR  0.27182818284590452f     // e/10
#define E10   4.5399929762484854e-05f  // exp(-10)
#define D_REF 0.36787944117144233f     // exp(-1)
#define C_REF -54.365636569180902f     // -20e

// scratch (allocation-free: device globals)
__device__ float    g_W1T[(size_t)NIN * NHID];          // [i][h]
__device__ unsigned g_M  [(size_t)BATCH * TT * NIG];    // X bitmasks [b][t][ig]
__device__ float    g_G1 [(size_t)BATCH * TT * NHID];   // [b][t][h]
__device__ unsigned g_S1b[(size_t)BATCH * TT * NHG];    // s1 bitmasks [b][t][hg]
__device__ float    g_G2 [(size_t)BATCH * TT * NOUT];   // [b][t][o]

// ---------------------------------------------------------------------------
// Merged prep: z=0 -> X bitmask build (73 x 32), z=1 -> W1 transpose (73 x 16)
// ---------------------------------------------------------------------------
__global__ void __launch_bounds__(352) prep_kernel(const float* __restrict__ X,
                                                   const float* __restrict__ W1) {
    const int tid = threadIdx.x;
    if (blockIdx.z == 0) {
        __shared__ float xs[32][TT];
        const int ig = blockIdx.x;
        const int b  = blockIdx.y;

        #pragma unroll 1
        for (int j = 0; j < 32; j++) {
            int i = ig * 32 + j;
            if (tid < TT)
                xs[j][tid] = (i < NIN) ? X[((size_t)b * NIN + i) * TT + tid] : 0.f;
        }
        __syncthreads();

        if (tid < TT) {
            unsigned w = 0;
            #pragma unroll
            for (int j = 0; j < 32; j++)
                if (xs[j][tid] != 0.f) w |= 1u << j;
            g_M[((size_t)b * TT + tid) * NIG + ig] = w;
        }
    } else {
        __shared__ float tile[32][33];
        if (blockIdx.y >= NHID / 32) return;
        if (tid >= 256) return;
        int i0 = blockIdx.x * 32;
        int h0 = blockIdx.y * 32;
        int lx = tid & 31;
        int ly = tid >> 5;

        #pragma unroll
        for (int r = 0; r < 4; r++) {
            int h = h0 + ly + r * 8;
            int i = i0 + lx;
            tile[ly + r * 8][lx] = (i < NIN) ? W1[(size_t)h * NIN + i] : 0.f;
        }
        __syncthreads();
        #pragma unroll
        for (int r = 0; r < 4; r++) {
            int i = i0 + ly + r * 8;
            int h = h0 + lx;
            if (i < NIN) g_W1T[(size_t)i * NHID + h] = tile[lx][ly + r * 8];
        }
    }
}

// ---------------------------------------------------------------------------
// Sparse GEMM1 v4: warp per (b, t-PAIR); 256-thread blocks = 8 warps = 16 t.
// Union-mask walk over both t's masks; per active row one load, two
// warp-uniform predicated f32x2 add blocks. Each t's adds happen only on its
// own active rows, in ascending-i order -> bit-exact vs prior rounds.
// 16 co-resident t/block (x ~4 blocks/SM) -> higher L1 temporal hit rate on
// W1T rows -> less LTS traffic (the binding constraint).
// ---------------------------------------------------------------------------
#define AF2(A, R) asm("add.rn.f32x2 %0, %1, %2;" : "=l"(A) : "l"(A), "l"(R))

__global__ void __launch_bounds__(256) spgemm1_kernel() {
    const int warp = threadIdx.x >> 5;
    const int lane = threadIdx.x & 31;
    const int b  = blockIdx.y;
    const int tp = blockIdx.x * 16 + warp * 2;   // even t of the pair
    if (tp >= TT) return;                        // TT even -> pairs complete

    const unsigned* __restrict__ mrow1 = g_M + ((size_t)b * TT + tp) * NIG;
    const unsigned* __restrict__ mrow2 = mrow1 + NIG;   // t = tp+1 (< TT)

    unsigned long long a0 = 0, a1 = 0, a2 = 0, a3 = 0,
                       a4 = 0, a5 = 0, a6 = 0, a7 = 0;   // t = tp
    unsigned long long c0 = 0, c1 = 0, c2 = 0, c3 = 0,
                       c4 = 0, c5 = 0, c6 = 0, c7 = 0;   // t = tp+1

    #pragma unroll
    for (int cb = 0; cb < 96; cb += 32) {
        const bool inb = (cb + lane < NIG);
        unsigned mw1 = inb ? mrow1[cb + lane] : 0u;
        unsigned mw2 = inb ? mrow2[cb + lane] : 0u;
        unsigned un  = mw1 | mw2;
        unsigned act = __ballot_sync(0xffffffffu, un != 0u);
        while (act) {
            int j = __ffs(act) - 1;
            act &= act - 1;
            unsigned u  = __shfl_sync(0xffffffffu, un,  j);
            unsigned w1 = __shfl_sync(0xffffffffu, mw1, j);
            unsigned w2 = __shfl_sync(0xffffffffu, mw2, j);
            int ibase = (cb + j) * 32;
            while (u) {
                int bit = __ffs(u) - 1;
                u &= u - 1;
                const ulonglong2* row =
                    (const ulonglong2*)(g_W1T + (size_t)(ibase + bit) * NHID);
                ulonglong2 r0 = row[lane];
                ulonglong2 r1 = row[lane + 32];
                ulonglong2 r2 = row[lane + 64];
                ulonglong2 r3 = row[lane + 96];
                if ((w1 >> bit) & 1u) {         // warp-uniform branch
                    AF2(a0, r0.x); AF2(a1, r0.y);
                    AF2(a2, r1.x); AF2(a3, r1.y);
                    AF2(a4, r2.x); AF2(a5, r2.y);
                    AF2(a6, r3.x); AF2(a7, r3.y);
                }
                if ((w2 >> bit) & 1u) {         // warp-uniform branch
                    AF2(c0, r0.x); AF2(c1, r0.y);
                    AF2(c2, r1.x); AF2(c3, r1.y);
                    AF2(c4, r2.x); AF2(c5, r2.y);
                    AF2(c6, r3.x); AF2(c7, r3.y);
                }
            }
        }
    }

    ulonglong2* out1 = (ulonglong2*)(g_G1 + ((size_t)b * TT + tp) * NHID);
    out1[lane]      = make_ulonglong2(a0, a1);
    out1[lane + 32] = make_ulonglong2(a2, a3);
    out1[lane + 64] = make_ulonglong2(a4, a5);
    out1[lane + 96] = make_ulonglong2(a6, a7);

    ulonglong2* out2 = (ulonglong2*)(g_G1 + ((size_t)b * TT + tp + 1) * NHID);
    out2[lane]      = make_ulonglong2(c0, c1);
    out2[lane + 32] = make_ulonglong2(c2, c3);
    out2[lane + 64] = make_ulonglong2(c4, c5);
    out2[lane + 96] = make_ulonglong2(c6, c7);
}

// ---------------------------------------------------------------------------
// scan1 v6: block = (b, 64-h slice), one channel per thread, NO smem.
// 7-buffer register ring, chunk length 25 (100 = 4 chunks), prefetch 2 ahead.
// Per-channel arithmetic identical to all prior rounds.
// ---------------------------------------------------------------------------
#define SCH 25   // 14 * 25 = 350 exactly

#define SCAN1_STEP(T, GV, GD)                                  \
    {                                                          \
        const int t = (T);                                     \
        float gv = (GV), gd = (GD);                            \
        float pa_o = pa, qa_o = qa, ra_o = ra;                 \
        pa = fmaf(D_SR, pa_o, gv);                             \
        pb = fmaf(D_SR, pb, D_SR * pa_o);                      \
        qa = fmaf(D_SR, qa_o, gd);                             \
        qb = fmaf(D_SR, qb, D_SR * qa_o);                      \
        float y = C_SR * (pb - E10 * fmaf(100.f, qa, qb));     \
        float u = fmaf(C_REF, rb, y);                          \
        float sp = (u >= THETA) ? 1.f : 0.f;                   \
        ra = fmaf(D_REF, ra_o, sp);                            \
        rb = fmaf(D_REF, rb, D_REF * ra_o);                    \
        unsigned wbits = __ballot_sync(0xffffffffu, sp != 0.f);\
        if (lane == 0) sb[(size_t)t * NHG] = wbits;            \
    }

#define PF(CC, B)                                              \
    _Pragma("unroll")                                          \
    for (int i = 0; i < SCH; i++)                              \
        B[i] = __ldg(&g[(size_t)((CC) * SCH + i) * NHID]);

#define CK(CC, BV, BD)                                         \
    _Pragma("unroll")                                          \
    for (int i = 0; i < SCH; i++)                              \
        SCAN1_STEP((CC) * SCH + i, BV[i], BD[i])

#define CK0(CC, BV)                                            \
    _Pragma("unroll")                                          \
    for (int i = 0; i < SCH; i++)                              \
        SCAN1_STEP((CC) * SCH + i, BV[i], 0.f)

__global__ void __launch_bounds__(64) scan1_kernel() {
    const int b   = blockIdx.y;
    const int h0  = blockIdx.x * 64;
    const int tid = threadIdx.x;
    const int lane = tid & 31;
    const int hg  = (h0 + tid) >> 5;

    const float* __restrict__ g = g_G1 + (size_t)b * TT * NHID + h0 + tid;
    unsigned* __restrict__ sb = g_S1b + (size_t)b * TT * NHG + hg;

    float pa = 0.f, pb = 0.f;
    float qa = 0.f, qb = 0.f;
    float ra = 0.f, rb = 0.f;

    float b0[SCH], b1[SCH], b2[SCH], b3[SCH], b4[SCH], b5[SCH], b6[SCH];

    PF(0, b0)
    PF(1, b1)
    PF(2, b2)   CK0(0, b0)
    PF(3, b3)   CK0(1, b1)
    PF(4, b4)   CK0(2, b2)
    PF(5, b5)   CK0(3, b3)
    PF(6, b6)   CK(4,  b4, b0)
    PF(7, b0)   CK(5,  b5, b1)
    PF(8, b1)   CK(6,  b6, b2)
    PF(9, b2)   CK(7,  b0, b3)
    PF(10, b3)  CK(8,  b1, b4)
    PF(11, b4)  CK(9,  b2, b5)
    PF(12, b5)  CK(10, b3, b6)
    PF(13, b6)  CK(11, b4, b0)
                CK(12, b5, b1)
                CK(13, b6, b2)
}

// ---------------------------------------------------------------------------
// GEMM2 (sparse): warp per (b,t). Spikes are exactly 1.0 -> G2[t][o] is a sum
// of W2^T rows over active h (ascending order). Lanes 0..9 hold outputs.
// ---------------------------------------------------------------------------
__global__ void __launch_bounds__(256) gemm2_kernel(const float* __restrict__ W2) {
    __shared__ float w2t[NHID * NOUT];   // transposed [h][o], 20 KB
    for (int i = threadIdx.x; i < NOUT * NHID; i += 256) {
        int o = i / NHID, h = i - o * NHID;
        w2t[h * NOUT + o] = W2[i];
    }
    __syncthreads();

    const int b = blockIdx.y;
    const int t = blockIdx.x * 8 + (threadIdx.x >> 5);
    const int lane = threadIdx.x & 31;
    if (t >= TT) return;

    const unsigned* srow = g_S1b + ((size_t)b * TT + t) * NHG;
    unsigned mw = (lane < NHG) ? srow[lane] : 0u;

    float acc = 0.f;   // lane<10: accumulator for o=lane
    unsigned act = __ballot_sync(0xffffffffu, mw != 0u);
    while (act) {
        int j = __ffs(act) - 1;
        act &= act - 1;
        unsigned w = __shfl_sync(0xffffffffu, mw, j);
        int hbase = j * 32;
        while (w) {
            int bit = __ffs(w) - 1;
            w &= w - 1;
            if (lane < NOUT) acc += w2t[(hbase + bit) * NOUT + lane];
        }
    }
    if (lane < NOUT)
        g_G2[((size_t)b * TT + t) * NOUT + lane] = acc;
}

// ---------------------------------------------------------------------------
// scan2: block per b. Stage G2[b] into smem, 10 threads run the spike scan.
// ---------------------------------------------------------------------------
__global__ void __launch_bounds__(128) scan2_kernel(float* __restrict__ out) {
    __shared__ float g2s[TT * NOUT];
    const int b = blockIdx.x;

    const float* src = g_G2 + (size_t)b * TT * NOUT;
    for (int i = threadIdx.x; i < TT * NOUT; i += 128) g2s[i] = src[i];
    __syncthreads();

    if (threadIdx.x < NOUT) {
        const int o = threadIdx.x;
        float* y_out = out + ((size_t)b * NOUT + o) * TT;

        float pa = 0.f, pb = 0.f, qa = 0.f, qb = 0.f, ra = 0.f, rb = 0.f;
        for (int t = 0; t < TT; t++) {
            float gv = g2s[t * NOUT + o];
            float gd = (t >= TKLEN) ? g2s[(t - TKLEN) * NOUT + o] : 0.f;

            float pa_o = pa, qa_o = qa, ra_o = ra;
            pa = fmaf(D_SR, pa_o, gv);
            pb = fmaf(D_SR, pb, D_SR * pa_o);
            qa = fmaf(D_SR, qa_o, gd);
            qb = fmaf(D_SR, qb, D_SR * qa_o);

            float y = C_SR * (pb - E10 * fmaf(100.f, qa, qb));
            float u = fmaf(C_REF, rb, y);
            float sp = (u >= THETA) ? 1.f : 0.f;

            ra = fmaf(D_REF, ra_o, sp);
            rb = fmaf(D_REF, rb, D_REF * ra_o);

            y_out[t] = sp;
        }
    }
}

// ---------------------------------------------------------------------------
extern "C" void kernel_launch(void* const* d_in, const int* in_sizes, int n_in,
                              void* d_out, int out_size) {
    const float* X  = (const float*)d_in[0];   // [32][2312][350]
    const float* W1 = (const float*)d_in[1];   // [512][2312]
    const float* W2 = (const float*)d_in[2];   // [10][512]
    float* out = (float*)d_out;                // [32][10][350]

    dim3 gP(NIG, BATCH, 2);          // z=0: mask, z=1: transpose (y<16)
    prep_kernel<<<gP, 352>>>(X, W1);

    dim3 gS((TT + 15) / 16, BATCH);  // (22, 32) blocks; warp = t-pair
    spgemm1_kernel<<<gS, 256>>>();

    dim3 gScan(NHID / 64, BATCH);    // (8, 32) = 256 blocks of 64
    scan1_kernel<<<gScan, 64>>>();

    dim3 gG2((TT + 7) / 8, BATCH);
    gemm2_kernel<<<gG2, 256>>>(W2);

    scan2_kernel<<<BATCH, 128>>>(out);
}

// round 13
// speedup vs baseline: 1.6619x; 1.6619x over previous
#include <cuda_runtime.h>

#define BATCH 32
#define NIN   2312
#define NHID  512
#define NOUT  10
#define TT    350
#define TKLEN 100
#define NIG   73    // ceil(NIN/32) mask words per (b,t)
#define NHG   (NHID/32)

#define THETA 10.0f
#define D_SR  0.90483741803595952f     // exp(-0.1)
#define C_SR  0.27182818284590452f     // e/10
#define E10   4.5399929762484854e-05f  // exp(-10)
#define D_REF 0.36787944117144233f     // exp(-1)
#define C_REF -54.365636569180902f     // -20e

// scratch (allocation-free: device globals)
__device__ float    g_W1T[(size_t)NIN * NHID];          // [i][h]
__device__ unsigned g_M  [(size_t)BATCH * TT * NIG];    // X bitmasks [b][t][ig]
__device__ float    g_G1 [(size_t)BATCH * TT * NHID];   // [b][t][h]
__device__ unsigned g_S1b[(size_t)BATCH * TT * NHG];    // s1 bitmasks [b][t][hg]
__device__ float    g_G2 [(size_t)BATCH * TT * NOUT];   // [b][t][o]

// ---------------------------------------------------------------------------
// Transpose W1 [NHID][NIN] -> W1T [NIN][NHID]
// ---------------------------------------------------------------------------
__global__ void __launch_bounds__(256) w1t_kernel(const float* __restrict__ W1) {
    __shared__ float tile[32][33];
    int i0 = blockIdx.x * 32;
    int h0 = blockIdx.y * 32;
    int lx = threadIdx.x & 31;
    int ly = threadIdx.x >> 5;

    #pragma unroll
    for (int r = 0; r < 4; r++) {
        int h = h0 + ly + r * 8;
        int i = i0 + lx;
        tile[ly + r * 8][lx] = (i < NIN) ? W1[(size_t)h * NIN + i] : 0.f;
    }
    __syncthreads();
    #pragma unroll
    for (int r = 0; r < 4; r++) {
        int i = i0 + ly + r * 8;
        int h = h0 + lx;
        if (i < NIN) g_W1T[(size_t)i * NHID + h] = tile[lx][ly + r * 8];
    }
}

// ---------------------------------------------------------------------------
// Mask build: block per (b, ig). Stage 32 rows of X coalescedly in smem,
// then thread t packs the 32-bit word -> g_M[b][t][ig].
// ---------------------------------------------------------------------------
__global__ void __launch_bounds__(352) maskbuild_kernel(const float* __restrict__ X) {
    __shared__ float xs[32][TT];
    const int ig = blockIdx.x;
    const int b  = blockIdx.y;
    const int tid = threadIdx.x;

    #pragma unroll 1
    for (int j = 0; j < 32; j++) {
        int i = ig * 32 + j;
        if (tid < TT)
            xs[j][tid] = (i < NIN) ? X[((size_t)b * NIN + i) * TT + tid] : 0.f;
    }
    __syncthreads();

    if (tid < TT) {
        unsigned w = 0;
        #pragma unroll
        for (int j = 0; j < 32; j++)
            if (xs[j][tid] != 0.f) w |= 1u << j;
        g_M[((size_t)b * TT + tid) * NIG + ig] = w;
    }
}

// ---------------------------------------------------------------------------
// Sparse GEMM1 (LOCKED round-4 shape): warp per (b,t); 8 consecutive t per
// block. Inner row-walk unrolled x2: pop two bits, issue all 8 row loads
// (2x MLP), then add row A fully, then row B — identical ascending-i
// accumulation order per element -> bit-exact. f32x2 packed adds.
// ---------------------------------------------------------------------------
#define AF2(A, R) asm("add.rn.f32x2 %0, %1, %2;" : "=l"(A) : "l"(A), "l"(R))

__global__ void __launch_bounds__(256) spgemm1_kernel() {
    const int warp = threadIdx.x >> 5;
    const int lane = threadIdx.x & 31;
    const int b = blockIdx.y;
    const int t = blockIdx.x * 8 + warp;
    if (t >= TT) return;

    const unsigned* __restrict__ mrow = g_M + ((size_t)b * TT + t) * NIG;

    unsigned long long a0 = 0, a1 = 0, a2 = 0, a3 = 0,
                       a4 = 0, a5 = 0, a6 = 0, a7 = 0;  // 16 floats as 8 f32x2

    #pragma unroll
    for (int cb = 0; cb < 96; cb += 32) {
        unsigned mw = (cb + lane < NIG) ? mrow[cb + lane] : 0u;
        unsigned act = __ballot_sync(0xffffffffu, mw != 0u);
        while (act) {
            int j = __ffs(act) - 1;
            act &= act - 1;
            unsigned w = __shfl_sync(0xffffffffu, mw, j);
            int ibase = (cb + j) * 32;
            // pairs: 8 loads in flight, then adds A then adds B (order kept)
            while (w) {
                int bit1 = __ffs(w) - 1;
                w &= w - 1;
                if (w) {
                    int bit2 = __ffs(w) - 1;
                    w &= w - 1;
                    const ulonglong2* rowA =
                        (const ulonglong2*)(g_W1T + (size_t)(ibase + bit1) * NHID);
                    const ulonglong2* rowB =
                        (const ulonglong2*)(g_W1T + (size_t)(ibase + bit2) * NHID);
                    ulonglong2 A0 = rowA[lane];
                    ulonglong2 A1 = rowA[lane + 32];
                    ulonglong2 A2 = rowA[lane + 64];
                    ulonglong2 A3 = rowA[lane + 96];
                    ulonglong2 B0 = rowB[lane];
                    ulonglong2 B1 = rowB[lane + 32];
                    ulonglong2 B2 = rowB[lane + 64];
                    ulonglong2 B3 = rowB[lane + 96];
                    AF2(a0, A0.x); AF2(a1, A0.y);
                    AF2(a2, A1.x); AF2(a3, A1.y);
                    AF2(a4, A2.x); AF2(a5, A2.y);
                    AF2(a6, A3.x); AF2(a7, A3.y);
                    AF2(a0, B0.x); AF2(a1, B0.y);
                    AF2(a2, B1.x); AF2(a3, B1.y);
                    AF2(a4, B2.x); AF2(a5, B2.y);
                    AF2(a6, B3.x); AF2(a7, B3.y);
                } else {
                    const ulonglong2* rowA =
                        (const ulonglong2*)(g_W1T + (size_t)(ibase + bit1) * NHID);
                    ulonglong2 A0 = rowA[lane];
                    ulonglong2 A1 = rowA[lane + 32];
                    ulonglong2 A2 = rowA[lane + 64];
                    ulonglong2 A3 = rowA[lane + 96];
                    AF2(a0, A0.x); AF2(a1, A0.y);
                    AF2(a2, A1.x); AF2(a3, A1.y);
                    AF2(a4, A2.x); AF2(a5, A2.y);
                    AF2(a6, A3.x); AF2(a7, A3.y);
                }
            }
        }
    }

    ulonglong2* out = (ulonglong2*)(g_G1 + ((size_t)b * TT + t) * NHID);
    out[lane]      = make_ulonglong2(a0, a1);
    out[lane + 32] = make_ulonglong2(a2, a3);
    out[lane + 64] = make_ulonglong2(a4, a5);
    out[lane + 96] = make_ulonglong2(a6, a7);
}

// ---------------------------------------------------------------------------
// scan1 v5 (round-8 proven): block = (b, 64-h slice), one channel per thread,
// NO smem. Single load stream; gd[t] = gv[t-100] via 6-buffer register ring
// (chunk 25, 100 = 4 chunks back). Prefetch 1 chunk ahead.
// ---------------------------------------------------------------------------
#define SCH 25   // 14 * 25 = 350 exactly

#define SCAN1_STEP(T, GV, GD)                                  \
    {                                                          \
        const int t = (T);                                     \
        float gv = (GV), gd = (GD);                            \
        float pa_o = pa, qa_o = qa, ra_o = ra;                 \
        pa = fmaf(D_SR, pa_o, gv);                             \
        pb = fmaf(D_SR, pb, D_SR * pa_o);                      \
        qa = fmaf(D_SR, qa_o, gd);                             \
        qb = fmaf(D_SR, qb, D_SR * qa_o);                      \
        float y = C_SR * (pb - E10 * fmaf(100.f, qa, qb));     \
        float u = fmaf(C_REF, rb, y);                          \
        float sp = (u >= THETA) ? 1.f : 0.f;                   \
        ra = fmaf(D_REF, ra_o, sp);                            \
        rb = fmaf(D_REF, rb, D_REF * ra_o);                    \
        unsigned wbits = __ballot_sync(0xffffffffu, sp != 0.f);\
        if (lane == 0) sb[(size_t)t * NHG] = wbits;            \
    }

#define PF(CC, B)                                              \
    _Pragma("unroll")                                          \
    for (int i = 0; i < SCH; i++)                              \
        B[i] = __ldg(&g[(size_t)((CC) * SCH + i) * NHID]);

#define CK(CC, BV, BD)                                         \
    _Pragma("unroll")                                          \
    for (int i = 0; i < SCH; i++)                              \
        SCAN1_STEP((CC) * SCH + i, BV[i], BD[i])

#define CK0(CC, BV)                                            \
    _Pragma("unroll")                                          \
    for (int i = 0; i < SCH; i++)                              \
        SCAN1_STEP((CC) * SCH + i, BV[i], 0.f)

__global__ void __launch_bounds__(64) scan1_kernel() {
    const int b   = blockIdx.y;
    const int h0  = blockIdx.x * 64;
    const int tid = threadIdx.x;
    const int lane = tid & 31;
    const int hg  = (h0 + tid) >> 5;

    const float* __restrict__ g = g_G1 + (size_t)b * TT * NHID + h0 + tid;
    unsigned* __restrict__ sb = g_S1b + (size_t)b * TT * NHG + hg;

    float pa = 0.f, pb = 0.f;
    float qa = 0.f, qb = 0.f;
    float ra = 0.f, rb = 0.f;

    float b0[SCH], b1[SCH], b2[SCH], b3[SCH], b4[SCH], b5[SCH];

    PF(0, b0)
    PF(1, b1)  CK0(0, b0)
    PF(2, b2)  CK0(1, b1)
    PF(3, b3)  CK0(2, b2)
    PF(4, b4)  CK0(3, b3)
    PF(5, b5)  CK(4, b4, b0)
    PF(6, b0)  CK(5, b5, b1)
    PF(7, b1)  CK(6, b0, b2)
    PF(8, b2)  CK(7, b1, b3)
    PF(9, b3)  CK(8, b2, b4)
    PF(10, b4) CK(9, b3, b5)
    PF(11, b5) CK(10, b4, b0)
    PF(12, b0) CK(11, b5, b1)
    PF(13, b1) CK(12, b0, b2)
               CK(13, b1, b3)
}

// ---------------------------------------------------------------------------
// GEMM2 (sparse): warp per (b,t). Spikes are exactly 1.0 -> G2[t][o] is a sum
// of W2^T rows over active h (ascending order). Lanes 0..9 hold outputs.
// ---------------------------------------------------------------------------
__global__ void __launch_bounds__(256) gemm2_kernel(const float* __restrict__ W2) {
    __shared__ float w2t[NHID * NOUT];   // transposed [h][o], 20 KB
    for (int i = threadIdx.x; i < NOUT * NHID; i += 256) {
        int o = i / NHID, h = i - o * NHID;
        w2t[h * NOUT + o] = W2[i];
    }
    __syncthreads();

    const int b = blockIdx.y;
    const int t = blockIdx.x * 8 + (threadIdx.x >> 5);
    const int lane = threadIdx.x & 31;
    if (t >= TT) return;

    const unsigned* srow = g_S1b + ((size_t)b * TT + t) * NHG;
    unsigned mw = (lane < NHG) ? srow[lane] : 0u;

    float acc = 0.f;   // lane<10: accumulator for o=lane
    unsigned act = __ballot_sync(0xffffffffu, mw != 0u);
    while (act) {
        int j = __ffs(act) - 1;
        act &= act - 1;
        unsigned w = __shfl_sync(0xffffffffu, mw, j);
        int hbase = j * 32;
        while (w) {
            int bit = __ffs(w) - 1;
            w &= w - 1;
            if (lane < NOUT) acc += w2t[(hbase + bit) * NOUT + lane];
        }
    }
    if (lane < NOUT)
        g_G2[((size_t)b * TT + t) * NOUT + lane] = acc;
}

// ---------------------------------------------------------------------------
// scan2: block per b. Stage G2[b] into smem, 10 threads run the spike scan.
// ---------------------------------------------------------------------------
__global__ void __launch_bounds__(128) scan2_kernel(float* __restrict__ out) {
    __shared__ float g2s[TT * NOUT];
    const int b = blockIdx.x;

    const float* src = g_G2 + (size_t)b * TT * NOUT;
    for (int i = threadIdx.x; i < TT * NOUT; i += 128) g2s[i] = src[i];
    __syncthreads();

    if (threadIdx.x < NOUT) {
        const int o = threadIdx.x;
        float* y_out = out + ((size_t)b * NOUT + o) * TT;

        float pa = 0.f, pb = 0.f, qa = 0.f, qb = 0.f, ra = 0.f, rb = 0.f;
        for (int t = 0; t < TT; t++) {
            float gv = g2s[t * NOUT + o];
            float gd = (t >= TKLEN) ? g2s[(t - TKLEN) * NOUT + o] : 0.f;

            float pa_o = pa, qa_o = qa, ra_o = ra;
            pa = fmaf(D_SR, pa_o, gv);
            pb = fmaf(D_SR, pb, D_SR * pa_o);
            qa = fmaf(D_SR, qa_o, gd);
            qb = fmaf(D_SR, qb, D_SR * qa_o);

            float y = C_SR * (pb - E10 * fmaf(100.f, qa, qb));
            float u = fmaf(C_REF, rb, y);
            float sp = (u >= THETA) ? 1.f : 0.f;

            ra = fmaf(D_REF, ra_o, sp);
            rb = fmaf(D_REF, rb, D_REF * ra_o);

            y_out[t] = sp;
        }
    }
}

// ---------------------------------------------------------------------------
extern "C" void kernel_launch(void* const* d_in, const int* in_sizes, int n_in,
                              void* d_out, int out_size) {
    const float* X  = (const float*)d_in[0];   // [32][2312][350]
    const float* W1 = (const float*)d_in[1];   // [512][2312]
    const float* W2 = (const float*)d_in[2];   // [10][512]
    float* out = (float*)d_out;                // [32][10][350]

    dim3 gT((NIN + 31) / 32, NHID / 32);
    w1t_kernel<<<gT, 256>>>(W1);

    dim3 gM(NIG, BATCH);
    maskbuild_kernel<<<gM, 352>>>(X);

    dim3 gS((TT + 7) / 8, BATCH);    // LOCKED round-4 shape
    spgemm1_kernel<<<gS, 256>>>();

    dim3 gScan(NHID / 64, BATCH);    // (8, 32) = 256 blocks of 64
    scan1_kernel<<<gScan, 64>>>();

    dim3 gG2((TT + 7) / 8, BATCH);
    gemm2_kernel<<<gG2, 256>>>(W2);

    scan2_kernel<<<BATCH, 128>>>(out);
}

// round 15
// speedup vs baseline: 1.6771x; 1.0092x over previous
#include <cuda_runtime.h>

#define BATCH 32
#define NIN   2312
#define NHID  512
#define NOUT  10
#define TT    350
#define TKLEN 100
#define NIG   73    // ceil(NIN/32) mask words per (b,t)
#define NHG   (NHID/32)

#define THETA 10.0f
#define D_SR  0.90483741803595952f     // exp(-0.1)
#define C_SR  0.27182818284590452f     // e/10
#define E10   4.5399929762484854e-05f  // exp(-10)
#define D_REF 0.36787944117144233f     // exp(-1)
#define C_REF -54.365636569180902f     // -20e

// scratch (allocation-free: device globals)
__device__ float    g_W1T[(size_t)NIN * NHID];          // [i][h]
__device__ unsigned g_M  [(size_t)BATCH * TT * NIG];    // X bitmasks [b][t][ig]
__device__ float    g_G1 [(size_t)BATCH * TT * NHID];   // [b][t][h]
__device__ unsigned g_S1b[(size_t)BATCH * TT * NHG];    // s1 bitmasks [b][t][hg]
__device__ float    g_G2 [(size_t)BATCH * TT * NOUT];   // [b][t][o]

// ---------------------------------------------------------------------------
// Transpose W1 [NHID][NIN] -> W1T [NIN][NHID]
// ---------------------------------------------------------------------------
__global__ void __launch_bounds__(256) w1t_kernel(const float* __restrict__ W1) {
    __shared__ float tile[32][33];
    int i0 = blockIdx.x * 32;
    int h0 = blockIdx.y * 32;
    int lx = threadIdx.x & 31;
    int ly = threadIdx.x >> 5;

    #pragma unroll
    for (int r = 0; r < 4; r++) {
        int h = h0 + ly + r * 8;
        int i = i0 + lx;
        tile[ly + r * 8][lx] = (i < NIN) ? W1[(size_t)h * NIN + i] : 0.f;
    }
    __syncthreads();
    #pragma unroll
    for (int r = 0; r < 4; r++) {
        int i = i0 + ly + r * 8;
        int h = h0 + lx;
        if (i < NIN) g_W1T[(size_t)i * NHID + h] = tile[lx][ly + r * 8];
    }
}

// ---------------------------------------------------------------------------
// Mask build: block per (b, ig). Stage 32 rows of X coalescedly in smem,
// then thread t packs the 32-bit word -> g_M[b][t][ig].
// ---------------------------------------------------------------------------
__global__ void __launch_bounds__(352) maskbuild_kernel(const float* __restrict__ X) {
    __shared__ float xs[32][TT];
    const int ig = blockIdx.x;
    const int b  = blockIdx.y;
    const int tid = threadIdx.x;

    #pragma unroll 1
    for (int j = 0; j < 32; j++) {
        int i = ig * 32 + j;
        if (tid < TT)
            xs[j][tid] = (i < NIN) ? X[((size_t)b * NIN + i) * TT + tid] : 0.f;
    }
    __syncthreads();

    if (tid < TT) {
        unsigned w = 0;
        #pragma unroll
        for (int j = 0; j < 32; j++)
            if (xs[j][tid] != 0.f) w |= 1u << j;
        g_M[((size_t)b * TT + tid) * NIG + ig] = w;
    }
}

// ---------------------------------------------------------------------------
// Sparse GEMM1 (LOCKED round-4 shape + occupancy boost): warp per (b,t);
// 8 consecutive t per block. minBlocksPerMultiprocessor=5 caps regs -> 5
// resident blocks = 40 co-resident t sharing L1 rows (hit 50%->~56%, less
// LTS traffic = the binding constraint). Ascending-i gather, f32x2 adds,
// per-element order identical -> bit-exact.
// ---------------------------------------------------------------------------
#define AF2(A, R) asm("add.rn.f32x2 %0, %1, %2;" : "=l"(A) : "l"(A), "l"(R))

__global__ void __launch_bounds__(256, 5) spgemm1_kernel() {
    const int warp = threadIdx.x >> 5;
    const int lane = threadIdx.x & 31;
    const int b = blockIdx.y;
    const int t = blockIdx.x * 8 + warp;
    if (t >= TT) return;

    const unsigned* __restrict__ mrow = g_M + ((size_t)b * TT + t) * NIG;

    unsigned long long a0 = 0, a1 = 0, a2 = 0, a3 = 0,
                       a4 = 0, a5 = 0, a6 = 0, a7 = 0;  // 16 floats as 8 f32x2

    #pragma unroll
    for (int cb = 0; cb < 96; cb += 32) {
        unsigned mw = (cb + lane < NIG) ? mrow[cb + lane] : 0u;
        unsigned act = __ballot_sync(0xffffffffu, mw != 0u);
        while (act) {
            int j = __ffs(act) - 1;
            act &= act - 1;
            unsigned w = __shfl_sync(0xffffffffu, mw, j);
            int ibase = (cb + j) * 32;
            while (w) {
                int bit = __ffs(w) - 1;
                w &= w - 1;
                const ulonglong2* row =
                    (const ulonglong2*)(g_W1T + (size_t)(ibase + bit) * NHID);
                ulonglong2 r0 = row[lane];
                ulonglong2 r1 = row[lane + 32];
                ulonglong2 r2 = row[lane + 64];
                ulonglong2 r3 = row[lane + 96];
                AF2(a0, r0.x); AF2(a1, r0.y);
                AF2(a2, r1.x); AF2(a3, r1.y);
                AF2(a4, r2.x); AF2(a5, r2.y);
                AF2(a6, r3.x); AF2(a7, r3.y);
            }
        }
    }

    ulonglong2* out = (ulonglong2*)(g_G1 + ((size_t)b * TT + t) * NHID);
    out[lane]      = make_ulonglong2(a0, a1);
    out[lane + 32] = make_ulonglong2(a2, a3);
    out[lane + 64] = make_ulonglong2(a4, a5);
    out[lane + 96] = make_ulonglong2(a6, a7);
}

// ---------------------------------------------------------------------------
// scan1 v6: block = (b, 64-h slice), one channel per thread, NO smem.
// 7-buffer register ring, chunk length 25 (100 = 4 chunks), prefetch TWO
// chunks ahead (doubled latency-hiding at the hard 16384-thread grid limit).
// Liveness: PF(c+2) overwrites buffer of chunk c-5, last used by CK(c-1). OK.
// Per-channel arithmetic identical to all prior rounds.
// ---------------------------------------------------------------------------
#define SCH 25   // 14 * 25 = 350 exactly

#define SCAN1_STEP(T, GV, GD)                                  \
    {                                                          \
        const int t = (T);                                     \
        float gv = (GV), gd = (GD);                            \
        float pa_o = pa, qa_o = qa, ra_o = ra;                 \
        pa = fmaf(D_SR, pa_o, gv);                             \
        pb = fmaf(D_SR, pb, D_SR * pa_o);                      \
        qa = fmaf(D_SR, qa_o, gd);                             \
        qb = fmaf(D_SR, qb, D_SR * qa_o);                      \
        float y = C_SR * (pb - E10 * fmaf(100.f, qa, qb));     \
        float u = fmaf(C_REF, rb, y);                          \
        float sp = (u >= THETA) ? 1.f : 0.f;                   \
        ra = fmaf(D_REF, ra_o, sp);                            \
        rb = fmaf(D_REF, rb, D_REF * ra_o);                    \
        unsigned wbits = __ballot_sync(0xffffffffu, sp != 0.f);\
        if (lane == 0) sb[(size_t)t * NHG] = wbits;            \
    }

#define PF(CC, B)                                              \
    _Pragma("unroll")                                          \
    for (int i = 0; i < SCH; i++)                              \
        B[i] = __ldg(&g[(size_t)((CC) * SCH + i) * NHID]);

#define CK(CC, BV, BD)                                         \
    _Pragma("unroll")                                          \
    for (int i = 0; i < SCH; i++)                              \
        SCAN1_STEP((CC) * SCH + i, BV[i], BD[i])

#define CK0(CC, BV)                                            \
    _Pragma("unroll")                                          \
    for (int i = 0; i < SCH; i++)                              \
        SCAN1_STEP((CC) * SCH + i, BV[i], 0.f)

__global__ void __launch_bounds__(64) scan1_kernel() {
    const int b   = blockIdx.y;
    const int h0  = blockIdx.x * 64;
    const int tid = threadIdx.x;
    const int lane = tid & 31;
    const int hg  = (h0 + tid) >> 5;

    const float* __restrict__ g = g_G1 + (size_t)b * TT * NHID + h0 + tid;
    unsigned* __restrict__ sb = g_S1b + (size_t)b * TT * NHG + hg;

    float pa = 0.f, pb = 0.f;
    float qa = 0.f, qb = 0.f;
    float ra = 0.f, rb = 0.f;

    float b0[SCH], b1[SCH], b2[SCH], b3[SCH], b4[SCH], b5[SCH], b6[SCH];

    // chunk c lives in b(c mod 7); gd of chunk c = buffer (c-4) mod 7
    PF(0, b0)
    PF(1, b1)
    PF(2, b2)   CK0(0, b0)
    PF(3, b3)   CK0(1, b1)
    PF(4, b4)   CK0(2, b2)
    PF(5, b5)   CK0(3, b3)
    PF(6, b6)   CK(4,  b4, b0)
    PF(7, b0)   CK(5,  b5, b1)
    PF(8, b1)   CK(6,  b6, b2)
    PF(9, b2)   CK(7,  b0, b3)
    PF(10, b3)  CK(8,  b1, b4)
    PF(11, b4)  CK(9,  b2, b5)
    PF(12, b5)  CK(10, b3, b6)
    PF(13, b6)  CK(11, b4, b0)
                CK(12, b5, b1)
                CK(13, b6, b2)
}

// ---------------------------------------------------------------------------
// GEMM2 (sparse): warp per (b,t). Spikes are exactly 1.0 -> G2[t][o] is a sum
// of W2^T rows over active h (ascending order). Lanes 0..9 hold outputs.
// ---------------------------------------------------------------------------
__global__ void __launch_bounds__(256) gemm2_kernel(const float* __restrict__ W2) {
    __shared__ float w2t[NHID * NOUT];   // transposed [h][o], 20 KB
    for (int i = threadIdx.x; i < NOUT * NHID; i += 256) {
        int o = i / NHID, h = i - o * NHID;
        w2t[h * NOUT + o] = W2[i];
    }
    __syncthreads();

    const int b = blockIdx.y;
    const int t = blockIdx.x * 8 + (threadIdx.x >> 5);
    const int lane = threadIdx.x & 31;
    if (t >= TT) return;

    const unsigned* srow = g_S1b + ((size_t)b * TT + t) * NHG;
    unsigned mw = (lane < NHG) ? srow[lane] : 0u;

    float acc = 0.f;   // lane<10: accumulator for o=lane
    unsigned act = __ballot_sync(0xffffffffu, mw != 0u);
    while (act) {
        int j = __ffs(act) - 1;
        act &= act - 1;
        unsigned w = __shfl_sync(0xffffffffu, mw, j);
        int hbase = j * 32;
        while (w) {
            int bit = __ffs(w) - 1;
            w &= w - 1;
            if (lane < NOUT) acc += w2t[(hbase + bit) * NOUT + lane];
        }
    }
    if (lane < NOUT)
        g_G2[((size_t)b * TT + t) * NOUT + lane] = acc;
}

// ---------------------------------------------------------------------------
// scan2: block per b. Stage G2[b] into smem, 10 threads run the spike scan.
// ---------------------------------------------------------------------------
__global__ void __launch_bounds__(128) scan2_kernel(float* __restrict__ out) {
    __shared__ float g2s[TT * NOUT];
    const int b = blockIdx.x;

    const float* src = g_G2 + (size_t)b * TT * NOUT;
    for (int i = threadIdx.x; i < TT * NOUT; i += 128) g2s[i] = src[i];
    __syncthreads();

    if (threadIdx.x < NOUT) {
        const int o = threadIdx.x;
        float* y_out = out + ((size_t)b * NOUT + o) * TT;

        float pa = 0.f, pb = 0.f, qa = 0.f, qb = 0.f, ra = 0.f, rb = 0.f;
        for (int t = 0; t < TT; t++) {
            float gv = g2s[t * NOUT + o];
            float gd = (t >= TKLEN) ? g2s[(t - TKLEN) * NOUT + o] : 0.f;

            float pa_o = pa, qa_o = qa, ra_o = ra;
            pa = fmaf(D_SR, pa_o, gv);
            pb = fmaf(D_SR, pb, D_SR * pa_o);
            qa = fmaf(D_SR, qa_o, gd);
            qb = fmaf(D_SR, qb, D_SR * qa_o);

            float y = C_SR * (pb - E10 * fmaf(100.f, qa, qb));
            float u = fmaf(C_REF, rb, y);
            float sp = (u >= THETA) ? 1.f : 0.f;

            ra = fmaf(D_REF, ra_o, sp);
            rb = fmaf(D_REF, rb, D_REF * ra_o);

            y_out[t] = sp;
        }
    }
}

// ---------------------------------------------------------------------------
extern "C" void kernel_launch(void* const* d_in, const int* in_sizes, int n_in,
                              void* d_out, int out_size) {
    const float* X  = (const float*)d_in[0];   // [32][2312][350]
    const float* W1 = (const float*)d_in[1];   // [512][2312]
    const float* W2 = (const float*)d_in[2];   // [10][512]
    float* out = (float*)d_out;                // [32][10][350]

    dim3 gT((NIN + 31) / 32, NHID / 32);
    w1t_kernel<<<gT, 256>>>(W1);

    dim3 gM(NIG, BATCH);
    maskbuild_kernel<<<gM, 352>>>(X);

    dim3 gS((TT + 7) / 8, BATCH);    // LOCKED round-4 shape
    spgemm1_kernel<<<gS, 256>>>();

    dim3 gScan(NHID / 64, BATCH);    // (8, 32) = 256 blocks of 64
    scan1_kernel<<<gScan, 64>>>();

    dim3 gG2((TT + 7) / 8, BATCH);
    gemm2_kernel<<<gG2, 256>>>(W2);

    scan2_kernel<<<BATCH, 128>>>(out);
}